// round 9
// baseline (speedup 1.0000x reference)
#include <cuda_runtime.h>
#include <math.h>

#define FEAT   512
#define HID    512
#define KNB    25
#define ALPHA  0.2f
#define GPC    16      // central nodes (agg rows) per CTA
#define NWARP  8       // 256 threads
#define ASTRIDE 516    // s_agg row stride in words (bank-conflict-free A frags)

// tiny scratch: w1 = W @ a[:H], w2 = W @ a[H:]   (small device globals: proven OK)
__device__ __align__(16) float g_w1[FEAT];
__device__ __align__(16) float g_w2[FEAT];

__global__ void wvec_kernel(const float* __restrict__ W,
                            const float* __restrict__ a_vec) {
    int f = blockIdx.x * blockDim.x + threadIdx.x;
    if (f >= FEAT) return;
    const float* row = W + (size_t)f * HID;
    float a1 = 0.f, a2 = 0.f;
    #pragma unroll 8
    for (int h = 0; h < HID; h++) {
        float w = row[h];
        a1 += w * a_vec[h];
        a2 += w * a_vec[HID + h];
    }
    g_w1[f] = a1;
    g_w2[f] = a2;
}

__device__ __forceinline__ unsigned f2tf32(float f) {
    unsigned u;
    asm("cvt.rna.tf32.f32 %0, %1;" : "=r"(u) : "f"(f));
    return u;
}

__device__ __forceinline__ void mma_tf32(float& d0, float& d1, float& d2, float& d3,
                                         unsigned a0, unsigned a1, unsigned a2, unsigned a3,
                                         unsigned b0, unsigned b1) {
    asm volatile(
        "mma.sync.aligned.m16n8k8.row.col.f32.tf32.tf32.f32 "
        "{%0,%1,%2,%3},{%4,%5,%6,%7},{%8,%9},{%0,%1,%2,%3};"
        : "+f"(d0), "+f"(d1), "+f"(d2), "+f"(d3)
        : "r"(a0), "r"(a1), "r"(a2), "r"(a3), "r"(b0), "r"(b1));
}

// Fused: gather + GAT attention + aggregation (fp32) + tf32 tensor-core GEMM + relu.
// 256 threads = 8 warps. Warp w gathers nodes (w) and (w+8) of this CTA's 16 rows.
// Epilogue: out[16 rows] = relu(s_agg[16x512] @ W[512x512]) via m16n8k8 tf32 mma;
// warp w owns output columns [w*64, w*64+64).
__global__ __launch_bounds__(256)
void fused_kernel(const int*   __restrict__ nodes,
                  const int*   __restrict__ neigh,
                  const float* __restrict__ feat,
                  const float* __restrict__ W,
                  float*       __restrict__ out,
                  int B, int num_nodes) {
    __shared__ unsigned s_agg[GPC * ASTRIDE];   // tf32 bits, 33 KB
    __shared__ float s_dot[GPC][26];
    __shared__ float s_attn[GPC][KNB];

    const int wid  = threadIdx.x >> 5;
    const int lane = threadIdx.x & 31;
    const int base = blockIdx.x * GPC;

    // ================= gather + attention + aggregation =================
    #pragma unroll
    for (int s = 0; s < 2; s++) {
        const int row = wid + NWARP * s;        // 0..15
        const int b   = base + row;

        if (b < B) {
            // ---- pass 1: dots with w1 (central) / w2 (neighbors) ----
            for (int r = 0; r < 26; r++) {
                int idx = (r == 0) ? nodes[b] : neigh[b * KNB + (r - 1)];
                idx = min(max(idx, 0), num_nodes - 1);
                const float* src = feat + (size_t)idx * FEAT;
                const float* wv  = (r == 0) ? g_w1 : g_w2;
                float part = 0.f;
                #pragma unroll
                for (int j = 0; j < 4; j++) {
                    int i = lane * 4 + 128 * j;
                    float4 v  = *(const float4*)(src + i);
                    float4 wc = *(const float4*)(wv + i);
                    part += v.x * wc.x + v.y * wc.y + v.z * wc.z + v.w * wc.w;
                }
                #pragma unroll
                for (int o = 16; o; o >>= 1)
                    part += __shfl_xor_sync(0xffffffffu, part, o);
                if (lane == 0) s_dot[row][r] = part;
            }
            __syncwarp();

            // ---- attention weights ----
            {
                float sct = s_dot[row][0];
                float e = 0.f;
                if (lane < KNB) {
                    float lg = sct + s_dot[row][1 + lane];
                    float lr = (lg > 0.f) ? lg : ALPHA * lg;
                    e = expf(-lr);
                }
                float tot = e;
                #pragma unroll
                for (int o = 16; o; o >>= 1)
                    tot += __shfl_xor_sync(0xffffffffu, tot, o);
                if (lane < KNB) s_attn[row][lane] = e / tot;
            }
            __syncwarp();

            // ---- pass 2: weighted aggregation (rows L1/L2-hot from pass 1) ----
            float4 acc[4];
            #pragma unroll
            for (int j = 0; j < 4; j++) acc[j] = make_float4(0.f, 0.f, 0.f, 0.f);
            for (int k = 0; k < KNB; k++) {
                int idx = neigh[b * KNB + k];
                idx = min(max(idx, 0), num_nodes - 1);
                float ak = s_attn[row][k];
                const float* src = feat + (size_t)idx * FEAT;
                #pragma unroll
                for (int j = 0; j < 4; j++) {
                    float4 v = *(const float4*)(src + lane * 4 + 128 * j);
                    acc[j].x += ak * v.x;  acc[j].y += ak * v.y;
                    acc[j].z += ak * v.z;  acc[j].w += ak * v.w;
                }
            }
            #pragma unroll
            for (int j = 0; j < 4; j++) {
                int c = lane * 4 + 128 * j;
                unsigned* dst = &s_agg[row * ASTRIDE + c];
                dst[0] = f2tf32(acc[j].x);
                dst[1] = f2tf32(acc[j].y);
                dst[2] = f2tf32(acc[j].z);
                dst[3] = f2tf32(acc[j].w);
            }
        } else {
            #pragma unroll
            for (int j = 0; j < 16; j++)
                s_agg[row * ASTRIDE + lane + 32 * j] = 0u;
        }
    }
    __syncthreads();

    // ================= epilogue: relu(s_agg @ W) via tf32 mma =================
    const int gid = lane >> 2;          // 0..7
    const int tig = lane & 3;           // 0..3
    const int n0  = wid * 64;           // this warp's 64-column slab

    float acc[8][4];
    #pragma unroll
    for (int t = 0; t < 8; t++)
        #pragma unroll
        for (int q = 0; q < 4; q++) acc[t][q] = 0.f;

    for (int k0 = 0; k0 < FEAT; k0 += 8) {
        const int ka = k0 + tig;
        // A fragments (m16k8, row-major): shared across all 8 n-tiles
        unsigned a0 = s_agg[gid * ASTRIDE + ka];
        unsigned a1 = s_agg[(gid + 8) * ASTRIDE + ka];
        unsigned a2 = s_agg[gid * ASTRIDE + ka + 4];
        unsigned a3 = s_agg[(gid + 8) * ASTRIDE + ka + 4];
        const float* wr0 = W + (size_t)ka * HID;
        const float* wr1 = wr0 + (size_t)4 * HID;
        #pragma unroll
        for (int t = 0; t < 8; t++) {
            int n = n0 + t * 8 + gid;
            unsigned b0 = f2tf32(wr0[n]);
            unsigned b1 = f2tf32(wr1[n]);
            mma_tf32(acc[t][0], acc[t][1], acc[t][2], acc[t][3],
                     a0, a1, a2, a3, b0, b1);
        }
    }

    // C layout: c0,c1 -> (gid, 2*tig{,+1}); c2,c3 -> (gid+8, same cols)
    const int bb0 = base + gid;
    const int bb1 = bb0 + 8;
    #pragma unroll
    for (int t = 0; t < 8; t++) {
        int col = n0 + t * 8 + 2 * tig;
        if (bb0 < B) {
            float2 o;
            o.x = fmaxf(acc[t][0], 0.f);
            o.y = fmaxf(acc[t][1], 0.f);
            *(float2*)(out + (size_t)bb0 * HID + col) = o;
        }
        if (bb1 < B) {
            float2 o;
            o.x = fmaxf(acc[t][2], 0.f);
            o.y = fmaxf(acc[t][3], 0.f);
            *(float2*)(out + (size_t)bb1 * HID + col) = o;
        }
    }
}

// ---------------- launch -----------------------------------------------------
// Inputs identified by element count (all six distinct):
//   nodes: 20000   neigh: 500000   feat: 51,200,000   W: 262144
//   a_vec: 1024    U: 729 (unused; eigh eigenvectors orthonormal => U@U^T = I)
extern "C" void kernel_launch(void* const* d_in, const int* in_sizes, int n_in,
                              void* d_out, int out_size) {
    const int*   nodes = nullptr;
    const int*   neigh = nullptr;
    const float* feat  = nullptr;
    const float* W     = nullptr;
    const float* a_vec = nullptr;
    long feat_elems = 0;

    long idx_sz[2] = {0, 0};
    const void* idx_ptr[2] = {nullptr, nullptr};
    int n_idx = 0;
    for (int i = 0; i < n_in; i++) {
        long n = in_sizes[i];
        if (n == 729) {
            // U — unused
        } else if (n == 1024) {
            a_vec = (const float*)d_in[i];
        } else if (n == 262144) {
            W = (const float*)d_in[i];
        } else if (n >= 1000000 && (n % FEAT) == 0) {
            feat = (const float*)d_in[i];
            feat_elems = n;
        } else if (n_idx < 2) {
            idx_sz[n_idx] = n; idx_ptr[n_idx] = d_in[i]; n_idx++;
        }
    }
    long nodes_n;
    if (idx_sz[0] <= idx_sz[1]) {
        nodes = (const int*)idx_ptr[0]; nodes_n = idx_sz[0];
        neigh = (const int*)idx_ptr[1];
    } else {
        nodes = (const int*)idx_ptr[1]; nodes_n = idx_sz[1];
        neigh = (const int*)idx_ptr[0];
    }

    float* out = (float*)d_out;
    int B = (int)nodes_n;
    int num_nodes = (int)(feat_elems / FEAT);

    wvec_kernel<<<(FEAT + 255) / 256, 256>>>(W, a_vec);
    fused_kernel<<<(B + GPC - 1) / GPC, 256>>>(nodes, neigh, feat, W, out,
                                               B, num_nodes);
}

// round 10
// speedup vs baseline: 1.3828x; 1.3828x over previous
#include <cuda_runtime.h>
#include <math.h>

#define FEAT   512
#define HID    512
#define KNB    25
#define ALPHA  0.2f
#define GPC    16      // central nodes (agg rows) per CTA
#define NTHR   512     // 16 warps, one row-set per warp
#define ASTRIDE 516    // s_agg row stride in words (bank-conflict-free A frags)

// tiny scratch: w1 = W @ a[:H], w2 = W @ a[H:]
__device__ __align__(16) float g_w1[FEAT];
__device__ __align__(16) float g_w2[FEAT];

__global__ void wvec_kernel(const float* __restrict__ W,
                            const float* __restrict__ a_vec) {
    int f = blockIdx.x * blockDim.x + threadIdx.x;
    if (f >= FEAT) return;
    const float* row = W + (size_t)f * HID;
    float a1 = 0.f, a2 = 0.f;
    #pragma unroll 8
    for (int h = 0; h < HID; h++) {
        float w = row[h];
        a1 += w * a_vec[h];
        a2 += w * a_vec[HID + h];
    }
    g_w1[f] = a1;
    g_w2[f] = a2;
}

__device__ __forceinline__ unsigned f2tf32(float f) {
    unsigned u;
    asm("cvt.rna.tf32.f32 %0, %1;" : "=r"(u) : "f"(f));
    return u;
}

__device__ __forceinline__ void mma_tf32(float& d0, float& d1, float& d2, float& d3,
                                         unsigned a0, unsigned a1, unsigned a2, unsigned a3,
                                         unsigned b0, unsigned b1) {
    asm volatile(
        "mma.sync.aligned.m16n8k8.row.col.f32.tf32.tf32.f32 "
        "{%0,%1,%2,%3},{%4,%5,%6,%7},{%8,%9},{%0,%1,%2,%3};"
        : "+f"(d0), "+f"(d1), "+f"(d2), "+f"(d3)
        : "r"(a0), "r"(a1), "r"(a2), "r"(a3), "r"(b0), "r"(b1));
}

// Fused: gather + GAT attention + aggregation (fp32) + tf32 tensor GEMM + relu.
// 512 threads = 16 warps; warp w owns agg row w (central node base+w).
// Epilogue: out[16x512] = relu(s_agg @ W); warp w owns 32 output columns.
__global__ __launch_bounds__(NTHR, 2)
void fused_kernel(const int*   __restrict__ nodes,
                  const int*   __restrict__ neigh,
                  const float* __restrict__ feat,
                  const float* __restrict__ W,
                  float*       __restrict__ out,
                  int B, int num_nodes) {
    __shared__ unsigned s_agg[GPC * ASTRIDE];   // tf32 bits, 33 KB
    __shared__ float s_dot[GPC][26];
    __shared__ float s_attn[GPC][KNB];
    __shared__ int   s_idx[GPC][26];

    const int wid  = threadIdx.x >> 5;          // 0..15 == agg row
    const int lane = threadIdx.x & 31;
    const int base = blockIdx.x * GPC;
    const int b    = base + wid;

    if (b < B) {
        // ---- prefetch + clamp all 26 indices (off the load critical path) ----
        if (lane < 26) {
            int idx = (lane == 0) ? nodes[b] : neigh[b * KNB + (lane - 1)];
            s_idx[wid][lane] = min(max(idx, 0), num_nodes - 1);
        }
        __syncwarp();

        // ---- central row dot with w1 (MLP 4) ----
        {
            const float* src = feat + (size_t)s_idx[wid][0] * FEAT;
            float p = 0.f;
            #pragma unroll
            for (int j = 0; j < 4; j++) {
                int i = lane * 4 + 128 * j;
                float4 v  = *(const float4*)(src + i);
                float4 wc = *(const float4*)(g_w1 + i);
                p += v.x * wc.x + v.y * wc.y + v.z * wc.z + v.w * wc.w;
            }
            #pragma unroll
            for (int o = 16; o; o >>= 1) p += __shfl_xor_sync(0xffffffffu, p, o);
            if (lane == 0) s_dot[wid][0] = p;
        }

        // ---- neighbor dots with w2, two rows per iteration (MLP 8) ----
        {
            float4 wc[4];
            #pragma unroll
            for (int j = 0; j < 4; j++)
                wc[j] = *(const float4*)(g_w2 + lane * 4 + 128 * j);

            for (int r = 1; r < 26; r += 2) {
                int rr = (r + 1 < 26) ? (r + 1) : 25;
                const float* s0 = feat + (size_t)s_idx[wid][r]  * FEAT;
                const float* s1 = feat + (size_t)s_idx[wid][rr] * FEAT;
                float4 v0[4], v1[4];
                #pragma unroll
                for (int j = 0; j < 4; j++) {
                    int i = lane * 4 + 128 * j;
                    v0[j] = *(const float4*)(s0 + i);
                    v1[j] = *(const float4*)(s1 + i);
                }
                float p0 = 0.f, p1 = 0.f;
                #pragma unroll
                for (int j = 0; j < 4; j++) {
                    p0 += v0[j].x * wc[j].x + v0[j].y * wc[j].y
                        + v0[j].z * wc[j].z + v0[j].w * wc[j].w;
                    p1 += v1[j].x * wc[j].x + v1[j].y * wc[j].y
                        + v1[j].z * wc[j].z + v1[j].w * wc[j].w;
                }
                #pragma unroll
                for (int o = 16; o; o >>= 1) {
                    p0 += __shfl_xor_sync(0xffffffffu, p0, o);
                    p1 += __shfl_xor_sync(0xffffffffu, p1, o);
                }
                if (lane == 0) {
                    s_dot[wid][r] = p0;
                    if (r + 1 < 26) s_dot[wid][r + 1] = p1;
                }
            }
        }
        __syncwarp();

        // ---- attention weights ----
        {
            float sct = s_dot[wid][0];
            float e = 0.f;
            if (lane < KNB) {
                float lg = sct + s_dot[wid][1 + lane];
                float lr = (lg > 0.f) ? lg : ALPHA * lg;
                e = expf(-lr);
            }
            float tot = e;
            #pragma unroll
            for (int o = 16; o; o >>= 1)
                tot += __shfl_xor_sync(0xffffffffu, tot, o);
            if (lane < KNB) s_attn[wid][lane] = e / tot;
        }
        __syncwarp();

        // ---- weighted aggregation, two neighbors per iteration (MLP 8) ----
        float4 acc[4];
        #pragma unroll
        for (int j = 0; j < 4; j++) acc[j] = make_float4(0.f, 0.f, 0.f, 0.f);
        for (int k = 0; k < KNB - 1; k += 2) {
            float a0 = s_attn[wid][k];
            float a1 = s_attn[wid][k + 1];
            const float* s0 = feat + (size_t)s_idx[wid][1 + k] * FEAT;
            const float* s1 = feat + (size_t)s_idx[wid][2 + k] * FEAT;
            float4 v0[4], v1[4];
            #pragma unroll
            for (int j = 0; j < 4; j++) {
                int i = lane * 4 + 128 * j;
                v0[j] = *(const float4*)(s0 + i);
                v1[j] = *(const float4*)(s1 + i);
            }
            #pragma unroll
            for (int j = 0; j < 4; j++) {
                acc[j].x += a0 * v0[j].x + a1 * v1[j].x;
                acc[j].y += a0 * v0[j].y + a1 * v1[j].y;
                acc[j].z += a0 * v0[j].z + a1 * v1[j].z;
                acc[j].w += a0 * v0[j].w + a1 * v1[j].w;
            }
        }
        {   // tail neighbor k = 24
            float a0 = s_attn[wid][KNB - 1];
            const float* s0 = feat + (size_t)s_idx[wid][KNB] * FEAT;
            #pragma unroll
            for (int j = 0; j < 4; j++) {
                float4 v = *(const float4*)(s0 + lane * 4 + 128 * j);
                acc[j].x += a0 * v.x;  acc[j].y += a0 * v.y;
                acc[j].z += a0 * v.z;  acc[j].w += a0 * v.w;
            }
        }
        #pragma unroll
        for (int j = 0; j < 4; j++) {
            int c = lane * 4 + 128 * j;
            unsigned* dst = &s_agg[wid * ASTRIDE + c];
            dst[0] = f2tf32(acc[j].x);
            dst[1] = f2tf32(acc[j].y);
            dst[2] = f2tf32(acc[j].z);
            dst[3] = f2tf32(acc[j].w);
        }
    } else {
        #pragma unroll
        for (int j = 0; j < 16; j++)
            s_agg[wid * ASTRIDE + lane + 32 * j] = 0u;
    }
    __syncthreads();

    // ================= epilogue: relu(s_agg @ W) via tf32 mma =================
    const int gid = lane >> 2;          // 0..7
    const int tig = lane & 3;           // 0..3
    const int n0  = wid * 32;           // this warp's 32-column slab

    float cacc[4][4];
    #pragma unroll
    for (int t = 0; t < 4; t++)
        #pragma unroll
        for (int q = 0; q < 4; q++) cacc[t][q] = 0.f;

    for (int k0 = 0; k0 < FEAT; k0 += 8) {
        const int ka = k0 + tig;
        unsigned a0 = s_agg[gid * ASTRIDE + ka];
        unsigned a1 = s_agg[(gid + 8) * ASTRIDE + ka];
        unsigned a2 = s_agg[gid * ASTRIDE + ka + 4];
        unsigned a3 = s_agg[(gid + 8) * ASTRIDE + ka + 4];
        const float* wr0 = W + (size_t)ka * HID;
        const float* wr1 = wr0 + (size_t)4 * HID;
        #pragma unroll
        for (int t = 0; t < 4; t++) {
            int n = n0 + t * 8 + gid;
            unsigned b0 = f2tf32(wr0[n]);
            unsigned b1 = f2tf32(wr1[n]);
            mma_tf32(cacc[t][0], cacc[t][1], cacc[t][2], cacc[t][3],
                     a0, a1, a2, a3, b0, b1);
        }
    }

    const int bb0 = base + gid;
    const int bb1 = bb0 + 8;
    #pragma unroll
    for (int t = 0; t < 4; t++) {
        int col = n0 + t * 8 + 2 * tig;
        if (bb0 < B) {
            float2 o;
            o.x = fmaxf(cacc[t][0], 0.f);
            o.y = fmaxf(cacc[t][1], 0.f);
            *(float2*)(out + (size_t)bb0 * HID + col) = o;
        }
        if (bb1 < B) {
            float2 o;
            o.x = fmaxf(cacc[t][2], 0.f);
            o.y = fmaxf(cacc[t][3], 0.f);
            *(float2*)(out + (size_t)bb1 * HID + col) = o;
        }
    }
}

// ---------------- launch -----------------------------------------------------
// Inputs identified by element count (all six distinct):
//   nodes: 20000   neigh: 500000   feat: 51,200,000   W: 262144
//   a_vec: 1024    U: 729 (unused; eigh eigenvectors orthonormal => U@U^T = I)
extern "C" void kernel_launch(void* const* d_in, const int* in_sizes, int n_in,
                              void* d_out, int out_size) {
    const int*   nodes = nullptr;
    const int*   neigh = nullptr;
    const float* feat  = nullptr;
    const float* W     = nullptr;
    const float* a_vec = nullptr;
    long feat_elems = 0;

    long idx_sz[2] = {0, 0};
    const void* idx_ptr[2] = {nullptr, nullptr};
    int n_idx = 0;
    for (int i = 0; i < n_in; i++) {
        long n = in_sizes[i];
        if (n == 729) {
            // U — unused
        } else if (n == 1024) {
            a_vec = (const float*)d_in[i];
        } else if (n == 262144) {
            W = (const float*)d_in[i];
        } else if (n >= 1000000 && (n % FEAT) == 0) {
            feat = (const float*)d_in[i];
            feat_elems = n;
        } else if (n_idx < 2) {
            idx_sz[n_idx] = n; idx_ptr[n_idx] = d_in[i]; n_idx++;
        }
    }
    long nodes_n;
    if (idx_sz[0] <= idx_sz[1]) {
        nodes = (const int*)idx_ptr[0]; nodes_n = idx_sz[0];
        neigh = (const int*)idx_ptr[1];
    } else {
        nodes = (const int*)idx_ptr[1]; nodes_n = idx_sz[1];
        neigh = (const int*)idx_ptr[0];
    }

    float* out = (float*)d_out;
    int B = (int)nodes_n;
    int num_nodes = (int)(feat_elems / FEAT);

    wvec_kernel<<<(FEAT + 255) / 256, 256>>>(W, a_vec);
    fused_kernel<<<(B + GPC - 1) / GPC, NTHR>>>(nodes, neigh, feat, W, out,
                                                B, num_nodes);
}

// round 12
// speedup vs baseline: 1.7909x; 1.2951x over previous
#include <cuda_runtime.h>
#include <math.h>

#define FEAT   512
#define HID    512
#define KNB    25
#define ALPHA  0.2f
#define GPC    16      // central nodes (agg rows) per CTA
#define NTHR   512     // 16 warps, one row per warp
#define ASTRIDE 516    // s_agg row stride in words (bank-conflict-free A frags)

// tiny scratch: w1 = W @ a[:H], w2 = W @ a[H:]
__device__ __align__(16) float g_w1[FEAT];
__device__ __align__(16) float g_w2[FEAT];

// warp-per-output-row: 8 warps/CTA, 64 CTAs
__global__ void wvec_kernel(const float* __restrict__ W,
                            const float* __restrict__ a_vec) {
    const int wid  = threadIdx.x >> 5;
    const int lane = threadIdx.x & 31;
    const int f    = blockIdx.x * 8 + wid;
    if (f >= FEAT) return;
    const float* row = W + (size_t)f * HID;
    float a1 = 0.f, a2 = 0.f;
    #pragma unroll
    for (int j = 0; j < 4; j++) {
        int i = lane * 4 + 128 * j;
        float4 w  = *(const float4*)(row + i);
        float4 v1 = *(const float4*)(a_vec + i);
        float4 v2 = *(const float4*)(a_vec + HID + i);
        a1 += w.x * v1.x + w.y * v1.y + w.z * v1.z + w.w * v1.w;
        a2 += w.x * v2.x + w.y * v2.y + w.z * v2.z + w.w * v2.w;
    }
    #pragma unroll
    for (int o = 16; o; o >>= 1) {
        a1 += __shfl_xor_sync(0xffffffffu, a1, o);
        a2 += __shfl_xor_sync(0xffffffffu, a2, o);
    }
    if (lane == 0) { g_w1[f] = a1; g_w2[f] = a2; }
}

__device__ __forceinline__ unsigned f2tf32(float f) {
    unsigned u;
    asm("cvt.rna.tf32.f32 %0, %1;" : "=r"(u) : "f"(f));
    return u;
}

__device__ __forceinline__ void mma_tf32(float& d0, float& d1, float& d2, float& d3,
                                         unsigned a0, unsigned a1, unsigned a2, unsigned a3,
                                         unsigned b0, unsigned b1) {
    asm volatile(
        "mma.sync.aligned.m16n8k8.row.col.f32.tf32.tf32.f32 "
        "{%0,%1,%2,%3},{%4,%5,%6,%7},{%8,%9},{%0,%1,%2,%3};"
        : "+f"(d0), "+f"(d1), "+f"(d2), "+f"(d3)
        : "r"(a0), "r"(a1), "r"(a2), "r"(a3), "r"(b0), "r"(b1));
}

// Fused single-pass: gather + unnormalized-softmax aggregation + tf32 GEMM + relu.
// agg = (Σ_k e_k h_k) / (Σ_k e_k), e_k = exp(-lrelu(s_ct + h_k·w2)).
// Each neighbor row is loaded from global EXACTLY ONCE (register-resident when
// weighted). 512 threads = 16 warps; warp w owns agg row w.
__global__ __launch_bounds__(NTHR, 2)
void fused_kernel(const int*   __restrict__ nodes,
                  const int*   __restrict__ neigh,
                  const float* __restrict__ feat,
                  const float* __restrict__ W,
                  float*       __restrict__ out,
                  int B, int num_nodes) {
    __shared__ unsigned s_agg[GPC * ASTRIDE];   // tf32 bits, 33 KB
    __shared__ int s_idx[GPC][26];

    const int wid  = threadIdx.x >> 5;          // 0..15 == agg row
    const int lane = threadIdx.x & 31;
    const int base = blockIdx.x * GPC;
    const int b    = base + wid;

    if (b < B) {
        // ---- prefetch + clamp all 26 indices ----
        if (lane < 26) {
            int idx = (lane == 0) ? nodes[b] : neigh[b * KNB + (lane - 1)];
            s_idx[wid][lane] = min(max(idx, 0), num_nodes - 1);
        }
        __syncwarp();

        // ---- central row dot with w1 ----
        float sct;
        {
            const float* src = feat + (size_t)s_idx[wid][0] * FEAT;
            float p = 0.f;
            #pragma unroll
            for (int j = 0; j < 4; j++) {
                int i = lane * 4 + 128 * j;
                float4 v  = *(const float4*)(src + i);
                float4 wc = *(const float4*)(g_w1 + i);
                p += v.x * wc.x + v.y * wc.y + v.z * wc.z + v.w * wc.w;
            }
            #pragma unroll
            for (int o = 16; o; o >>= 1) p += __shfl_xor_sync(0xffffffffu, p, o);
            sct = p;    // all lanes hold s_ct
        }

        // ---- single pass over neighbors, two rows per iteration (MLP 8) ----
        float4 acc[4];
        #pragma unroll
        for (int j = 0; j < 4; j++) acc[j] = make_float4(0.f, 0.f, 0.f, 0.f);
        float esum = 0.f;

        for (int k = 0; k < KNB - 1; k += 2) {
            const float* s0 = feat + (size_t)s_idx[wid][1 + k] * FEAT;
            const float* s1 = feat + (size_t)s_idx[wid][2 + k] * FEAT;
            float4 v0[4], v1[4];
            #pragma unroll
            for (int j = 0; j < 4; j++) {
                int i = lane * 4 + 128 * j;
                v0[j] = *(const float4*)(s0 + i);
                v1[j] = *(const float4*)(s1 + i);
            }
            float p0 = 0.f, p1 = 0.f;
            #pragma unroll
            for (int j = 0; j < 4; j++) {
                float4 wc = *(const float4*)(g_w2 + lane * 4 + 128 * j);
                p0 += v0[j].x * wc.x + v0[j].y * wc.y + v0[j].z * wc.z + v0[j].w * wc.w;
                p1 += v1[j].x * wc.x + v1[j].y * wc.y + v1[j].z * wc.z + v1[j].w * wc.w;
            }
            #pragma unroll
            for (int o = 16; o; o >>= 1) {
                p0 += __shfl_xor_sync(0xffffffffu, p0, o);
                p1 += __shfl_xor_sync(0xffffffffu, p1, o);
            }
            float lg0 = sct + p0, lg1 = sct + p1;
            float lr0 = (lg0 > 0.f) ? lg0 : ALPHA * lg0;
            float lr1 = (lg1 > 0.f) ? lg1 : ALPHA * lg1;
            float e0 = expf(-lr0), e1 = expf(-lr1);
            esum += e0 + e1;
            #pragma unroll
            for (int j = 0; j < 4; j++) {
                acc[j].x += e0 * v0[j].x + e1 * v1[j].x;
                acc[j].y += e0 * v0[j].y + e1 * v1[j].y;
                acc[j].z += e0 * v0[j].z + e1 * v1[j].z;
                acc[j].w += e0 * v0[j].w + e1 * v1[j].w;
            }
        }
        {   // tail neighbor (k = 24)
            const float* s0 = feat + (size_t)s_idx[wid][KNB] * FEAT;
            float4 v0[4];
            #pragma unroll
            for (int j = 0; j < 4; j++)
                v0[j] = *(const float4*)(s0 + lane * 4 + 128 * j);
            float p0 = 0.f;
            #pragma unroll
            for (int j = 0; j < 4; j++) {
                float4 wc = *(const float4*)(g_w2 + lane * 4 + 128 * j);
                p0 += v0[j].x * wc.x + v0[j].y * wc.y + v0[j].z * wc.z + v0[j].w * wc.w;
            }
            #pragma unroll
            for (int o = 16; o; o >>= 1) p0 += __shfl_xor_sync(0xffffffffu, p0, o);
            float lg0 = sct + p0;
            float lr0 = (lg0 > 0.f) ? lg0 : ALPHA * lg0;
            float e0 = expf(-lr0);
            esum += e0;
            #pragma unroll
            for (int j = 0; j < 4; j++) {
                acc[j].x += e0 * v0[j].x;  acc[j].y += e0 * v0[j].y;
                acc[j].z += e0 * v0[j].z;  acc[j].w += e0 * v0[j].w;
            }
        }

        const float inv = 1.f / esum;
        #pragma unroll
        for (int j = 0; j < 4; j++) {
            int c = lane * 4 + 128 * j;
            unsigned* dst = &s_agg[wid * ASTRIDE + c];
            dst[0] = f2tf32(acc[j].x * inv);
            dst[1] = f2tf32(acc[j].y * inv);
            dst[2] = f2tf32(acc[j].z * inv);
            dst[3] = f2tf32(acc[j].w * inv);
        }
    } else {
        #pragma unroll
        for (int j = 0; j < 16; j++)
            s_agg[wid * ASTRIDE + lane + 32 * j] = 0u;
    }
    __syncthreads();

    // ================= epilogue: relu(s_agg @ W) via tf32 mma =================
    const int gid = lane >> 2;          // 0..7
    const int tig = lane & 3;           // 0..3
    const int n0  = wid * 32;           // this warp's 32-column slab

    float cacc[4][4];
    #pragma unroll
    for (int t = 0; t < 4; t++)
        #pragma unroll
        for (int q = 0; q < 4; q++) cacc[t][q] = 0.f;

    for (int k0 = 0; k0 < FEAT; k0 += 8) {
        const int ka = k0 + tig;
        unsigned a0 = s_agg[gid * ASTRIDE + ka];
        unsigned a1 = s_agg[(gid + 8) * ASTRIDE + ka];
        unsigned a2 = s_agg[gid * ASTRIDE + ka + 4];
        unsigned a3 = s_agg[(gid + 8) * ASTRIDE + ka + 4];
        const float* wr0 = W + (size_t)ka * HID;
        const float* wr1 = wr0 + (size_t)4 * HID;
        #pragma unroll
        for (int t = 0; t < 4; t++) {
            int n = n0 + t * 8 + gid;
            unsigned b0 = f2tf32(wr0[n]);
            unsigned b1 = f2tf32(wr1[n]);
            mma_tf32(cacc[t][0], cacc[t][1], cacc[t][2], cacc[t][3],
                     a0, a1, a2, a3, b0, b1);
        }
    }

    const int bb0 = base + gid;
    const int bb1 = bb0 + 8;
    #pragma unroll
    for (int t = 0; t < 4; t++) {
        int col = n0 + t * 8 + 2 * tig;
        if (bb0 < B) {
            float2 o;
            o.x = fmaxf(cacc[t][0], 0.f);
            o.y = fmaxf(cacc[t][1], 0.f);
            *(float2*)(out + (size_t)bb0 * HID + col) = o;
        }
        if (bb1 < B) {
            float2 o;
            o.x = fmaxf(cacc[t][2], 0.f);
            o.y = fmaxf(cacc[t][3], 0.f);
            *(float2*)(out + (size_t)bb1 * HID + col) = o;
        }
    }
}

// ---------------- launch -----------------------------------------------------
// Inputs identified by element count (all six distinct):
//   nodes: 20000   neigh: 500000   feat: 51,200,000   W: 262144
//   a_vec: 1024    U: 729 (unused; eigh eigenvectors orthonormal => U@U^T = I)
extern "C" void kernel_launch(void* const* d_in, const int* in_sizes, int n_in,
                              void* d_out, int out_size) {
    const int*   nodes = nullptr;
    const int*   neigh = nullptr;
    const float* feat  = nullptr;
    const float* W     = nullptr;
    const float* a_vec = nullptr;
    long feat_elems = 0;

    long idx_sz[2] = {0, 0};
    const void* idx_ptr[2] = {nullptr, nullptr};
    int n_idx = 0;
    for (int i = 0; i < n_in; i++) {
        long n = in_sizes[i];
        if (n == 729) {
            // U — unused
        } else if (n == 1024) {
            a_vec = (const float*)d_in[i];
        } else if (n == 262144) {
            W = (const float*)d_in[i];
        } else if (n >= 1000000 && (n % FEAT) == 0) {
            feat = (const float*)d_in[i];
            feat_elems = n;
        } else if (n_idx < 2) {
            idx_sz[n_idx] = n; idx_ptr[n_idx] = d_in[i]; n_idx++;
        }
    }
    long nodes_n;
    if (idx_sz[0] <= idx_sz[1]) {
        nodes = (const int*)idx_ptr[0]; nodes_n = idx_sz[0];
        neigh = (const int*)idx_ptr[1];
    } else {
        nodes = (const int*)idx_ptr[1]; nodes_n = idx_sz[1];
        neigh = (const int*)idx_ptr[0];
    }

    float* out = (float*)d_out;
    int B = (int)nodes_n;
    int num_nodes = (int)(feat_elems / FEAT);

    wvec_kernel<<<64, 256>>>(W, a_vec);
    fused_kernel<<<(B + GPC - 1) / GPC, NTHR>>>(nodes, neigh, feat, W, out,
                                                B, num_nodes);
}

// round 13
// speedup vs baseline: 1.8671x; 1.0426x over previous
#include <cuda_runtime.h>
#include <math.h>

#define FEAT   512
#define HID    512
#define KNB    25
#define ALPHA  0.2f
#define GPC    32      // central nodes (agg rows) per CTA, one per warp
#define NTHR   1024    // 32 warps
#define ASTRIDE 516    // s_agg row stride in words (bank-conflict-free A frags)

// tiny scratch: w1 = W @ a[:H], w2 = W @ a[H:]
__device__ __align__(16) float g_w1[FEAT];
__device__ __align__(16) float g_w2[FEAT];

// warp-per-output-row: 8 warps/CTA, 64 CTAs
__global__ void wvec_kernel(const float* __restrict__ W,
                            const float* __restrict__ a_vec) {
    const int wid  = threadIdx.x >> 5;
    const int lane = threadIdx.x & 31;
    const int f    = blockIdx.x * 8 + wid;
    if (f >= FEAT) return;
    const float* row = W + (size_t)f * HID;
    float a1 = 0.f, a2 = 0.f;
    #pragma unroll
    for (int j = 0; j < 4; j++) {
        int i = lane * 4 + 128 * j;
        float4 w  = *(const float4*)(row + i);
        float4 v1 = *(const float4*)(a_vec + i);
        float4 v2 = *(const float4*)(a_vec + HID + i);
        a1 += w.x * v1.x + w.y * v1.y + w.z * v1.z + w.w * v1.w;
        a2 += w.x * v2.x + w.y * v2.y + w.z * v2.z + w.w * v2.w;
    }
    #pragma unroll
    for (int o = 16; o; o >>= 1) {
        a1 += __shfl_xor_sync(0xffffffffu, a1, o);
        a2 += __shfl_xor_sync(0xffffffffu, a2, o);
    }
    if (lane == 0) { g_w1[f] = a1; g_w2[f] = a2; }
}

__device__ __forceinline__ unsigned f2tf32(float f) {
    unsigned u;
    asm("cvt.rna.tf32.f32 %0, %1;" : "=r"(u) : "f"(f));
    return u;
}

__device__ __forceinline__ void mma_tf32(float& d0, float& d1, float& d2, float& d3,
                                         unsigned a0, unsigned a1, unsigned a2, unsigned a3,
                                         unsigned b0, unsigned b1) {
    asm volatile(
        "mma.sync.aligned.m16n8k8.row.col.f32.tf32.tf32.f32 "
        "{%0,%1,%2,%3},{%4,%5,%6,%7},{%8,%9},{%0,%1,%2,%3};"
        : "+f"(d0), "+f"(d1), "+f"(d2), "+f"(d3)
        : "r"(a0), "r"(a1), "r"(a2), "r"(a3), "r"(b0), "r"(b1));
}

// Fused single-pass: gather + unnormalized-softmax aggregation + tf32 GEMM + relu.
// agg = (Σ_k e_k h_k) / (Σ_k e_k), e_k = exp(-lrelu(s_ct + h_k·w2)).
// 1024 threads = 32 warps; warp w owns agg row w. w1/w2 staged in smem (LDS).
// Epilogue: out[32x512] = relu(s_agg @ W); warp w owns 16 output columns.
__global__ __launch_bounds__(NTHR, 1)
void fused_kernel(const int*   __restrict__ nodes,
                  const int*   __restrict__ neigh,
                  const float* __restrict__ feat,
                  const float* __restrict__ W,
                  float*       __restrict__ out,
                  int B, int num_nodes) {
    __shared__ unsigned s_agg[GPC * ASTRIDE];   // tf32 bits, 66 KB
    __shared__ int s_idx[GPC][26];
    __shared__ __align__(16) float s_w1[FEAT];
    __shared__ __align__(16) float s_w2[FEAT];

    const int wid  = threadIdx.x >> 5;          // 0..31 == agg row
    const int lane = threadIdx.x & 31;
    const int base = blockIdx.x * GPC;
    const int b    = base + wid;

    // stage w1/w2 into smem (threads 0..1023 cover 2x512)
    if (threadIdx.x < 512)       s_w1[threadIdx.x] = g_w1[threadIdx.x];
    else                         s_w2[threadIdx.x - 512] = g_w2[threadIdx.x - 512];

    // prefetch + clamp all 26 indices
    if (b < B && lane < 26) {
        int idx = (lane == 0) ? nodes[b] : neigh[b * KNB + (lane - 1)];
        s_idx[wid][lane] = min(max(idx, 0), num_nodes - 1);
    }
    __syncthreads();

    if (b < B) {
        // ---- central row dot with w1 ----
        float sct;
        {
            const float* src = feat + (size_t)s_idx[wid][0] * FEAT;
            float p = 0.f;
            #pragma unroll
            for (int j = 0; j < 4; j++) {
                int i = lane * 4 + 128 * j;
                float4 v  = *(const float4*)(src + i);
                float4 wc = *(const float4*)(s_w1 + i);
                p += v.x * wc.x + v.y * wc.y + v.z * wc.z + v.w * wc.w;
            }
            #pragma unroll
            for (int o = 16; o; o >>= 1) p += __shfl_xor_sync(0xffffffffu, p, o);
            sct = p;
        }

        // ---- single pass over neighbors, two rows per iteration (MLP 8) ----
        float4 acc[4];
        #pragma unroll
        for (int j = 0; j < 4; j++) acc[j] = make_float4(0.f, 0.f, 0.f, 0.f);
        float esum = 0.f;

        for (int k = 0; k < KNB - 1; k += 2) {
            const float* s0 = feat + (size_t)s_idx[wid][1 + k] * FEAT;
            const float* s1 = feat + (size_t)s_idx[wid][2 + k] * FEAT;
            float4 v0[4], v1[4];
            #pragma unroll
            for (int j = 0; j < 4; j++) {
                int i = lane * 4 + 128 * j;
                v0[j] = *(const float4*)(s0 + i);
                v1[j] = *(const float4*)(s1 + i);
            }
            float p0 = 0.f, p1 = 0.f;
            #pragma unroll
            for (int j = 0; j < 4; j++) {
                float4 wc = *(const float4*)(s_w2 + lane * 4 + 128 * j);
                p0 += v0[j].x * wc.x + v0[j].y * wc.y + v0[j].z * wc.z + v0[j].w * wc.w;
                p1 += v1[j].x * wc.x + v1[j].y * wc.y + v1[j].z * wc.z + v1[j].w * wc.w;
            }
            #pragma unroll
            for (int o = 16; o; o >>= 1) {
                p0 += __shfl_xor_sync(0xffffffffu, p0, o);
                p1 += __shfl_xor_sync(0xffffffffu, p1, o);
            }
            float lg0 = sct + p0, lg1 = sct + p1;
            float lr0 = (lg0 > 0.f) ? lg0 : ALPHA * lg0;
            float lr1 = (lg1 > 0.f) ? lg1 : ALPHA * lg1;
            float e0 = __expf(-lr0), e1 = __expf(-lr1);
            esum += e0 + e1;
            #pragma unroll
            for (int j = 0; j < 4; j++) {
                acc[j].x += e0 * v0[j].x + e1 * v1[j].x;
                acc[j].y += e0 * v0[j].y + e1 * v1[j].y;
                acc[j].z += e0 * v0[j].z + e1 * v1[j].z;
                acc[j].w += e0 * v0[j].w + e1 * v1[j].w;
            }
        }
        {   // tail neighbor (k = 24)
            const float* s0 = feat + (size_t)s_idx[wid][KNB] * FEAT;
            float4 v0[4];
            #pragma unroll
            for (int j = 0; j < 4; j++)
                v0[j] = *(const float4*)(s0 + lane * 4 + 128 * j);
            float p0 = 0.f;
            #pragma unroll
            for (int j = 0; j < 4; j++) {
                float4 wc = *(const float4*)(s_w2 + lane * 4 + 128 * j);
                p0 += v0[j].x * wc.x + v0[j].y * wc.y + v0[j].z * wc.z + v0[j].w * wc.w;
            }
            #pragma unroll
            for (int o = 16; o; o >>= 1) p0 += __shfl_xor_sync(0xffffffffu, p0, o);
            float lg0 = sct + p0;
            float lr0 = (lg0 > 0.f) ? lg0 : ALPHA * lg0;
            float e0 = __expf(-lr0);
            esum += e0;
            #pragma unroll
            for (int j = 0; j < 4; j++) {
                acc[j].x += e0 * v0[j].x;  acc[j].y += e0 * v0[j].y;
                acc[j].z += e0 * v0[j].z;  acc[j].w += e0 * v0[j].w;
            }
        }

        const float inv = 1.f / esum;
        #pragma unroll
        for (int j = 0; j < 4; j++) {
            int c = lane * 4 + 128 * j;
            unsigned* dst = &s_agg[wid * ASTRIDE + c];
            dst[0] = f2tf32(acc[j].x * inv);
            dst[1] = f2tf32(acc[j].y * inv);
            dst[2] = f2tf32(acc[j].z * inv);
            dst[3] = f2tf32(acc[j].w * inv);
        }
    } else {
        #pragma unroll
        for (int j = 0; j < 16; j++)
            s_agg[wid * ASTRIDE + lane + 32 * j] = 0u;
    }
    __syncthreads();

    // ============ epilogue: relu(s_agg[32x512] @ W) via tf32 mma ============
    // warp w owns cols [w*16, w*16+16); 2 row-tiles (m16) x 2 col-tiles (n8).
    const int gid = lane >> 2;          // 0..7
    const int tig = lane & 3;           // 0..3
    const int n0  = wid * 16;

    float cacc[2][2][4];
    #pragma unroll
    for (int r = 0; r < 2; r++)
        #pragma unroll
        for (int t = 0; t < 2; t++)
            #pragma unroll
            for (int q = 0; q < 4; q++) cacc[r][t][q] = 0.f;

    for (int k0 = 0; k0 < FEAT; k0 += 8) {
        const int ka = k0 + tig;
        const float* wr0 = W + (size_t)ka * HID;
        const float* wr1 = wr0 + (size_t)4 * HID;
        unsigned bf[2][2];
        #pragma unroll
        for (int t = 0; t < 2; t++) {
            int n = n0 + t * 8 + gid;
            bf[t][0] = f2tf32(wr0[n]);
            bf[t][1] = f2tf32(wr1[n]);
        }
        #pragma unroll
        for (int r = 0; r < 2; r++) {
            int row0 = gid + 16 * r;
            unsigned a0 = s_agg[row0 * ASTRIDE + ka];
            unsigned a1 = s_agg[(row0 + 8) * ASTRIDE + ka];
            unsigned a2 = s_agg[row0 * ASTRIDE + ka + 4];
            unsigned a3 = s_agg[(row0 + 8) * ASTRIDE + ka + 4];
            #pragma unroll
            for (int t = 0; t < 2; t++)
                mma_tf32(cacc[r][t][0], cacc[r][t][1], cacc[r][t][2], cacc[r][t][3],
                         a0, a1, a2, a3, bf[t][0], bf[t][1]);
        }
    }

    #pragma unroll
    for (int r = 0; r < 2; r++) {
        const int bb0 = base + gid + 16 * r;
        const int bb1 = bb0 + 8;
        #pragma unroll
        for (int t = 0; t < 2; t++) {
            int col = n0 + t * 8 + 2 * tig;
            if (bb0 < B) {
                float2 o;
                o.x = fmaxf(cacc[r][t][0], 0.f);
                o.y = fmaxf(cacc[r][t][1], 0.f);
                *(float2*)(out + (size_t)bb0 * HID + col) = o;
            }
            if (bb1 < B) {
                float2 o;
                o.x = fmaxf(cacc[r][t][2], 0.f);
                o.y = fmaxf(cacc[r][t][3], 0.f);
                *(float2*)(out + (size_t)bb1 * HID + col) = o;
            }
        }
    }
}

// ---------------- launch -----------------------------------------------------
// Inputs identified by element count (all six distinct):
//   nodes: 20000   neigh: 500000   feat: 51,200,000   W: 262144
//   a_vec: 1024    U: 729 (unused; eigh eigenvectors orthonormal => U@U^T = I)
extern "C" void kernel_launch(void* const* d_in, const int* in_sizes, int n_in,
                              void* d_out, int out_size) {
    const int*   nodes = nullptr;
    const int*   neigh = nullptr;
    const float* feat  = nullptr;
    const float* W     = nullptr;
    const float* a_vec = nullptr;
    long feat_elems = 0;

    long idx_sz[2] = {0, 0};
    const void* idx_ptr[2] = {nullptr, nullptr};
    int n_idx = 0;
    for (int i = 0; i < n_in; i++) {
        long n = in_sizes[i];
        if (n == 729) {
            // U — unused
        } else if (n == 1024) {
            a_vec = (const float*)d_in[i];
        } else if (n == 262144) {
            W = (const float*)d_in[i];
        } else if (n >= 1000000 && (n % FEAT) == 0) {
            feat = (const float*)d_in[i];
            feat_elems = n;
        } else if (n_idx < 2) {
            idx_sz[n_idx] = n; idx_ptr[n_idx] = d_in[i]; n_idx++;
        }
    }
    long nodes_n;
    if (idx_sz[0] <= idx_sz[1]) {
        nodes = (const int*)idx_ptr[0]; nodes_n = idx_sz[0];
        neigh = (const int*)idx_ptr[1];
    } else {
        nodes = (const int*)idx_ptr[1]; nodes_n = idx_sz[1];
        neigh = (const int*)idx_ptr[0];
    }

    float* out = (float*)d_out;
    int B = (int)nodes_n;
    int num_nodes = (int)(feat_elems / FEAT);

    wvec_kernel<<<64, 256>>>(W, a_vec);
    fused_kernel<<<(B + GPC - 1) / GPC, NTHR>>>(nodes, neigh, feat, W, out,
                                                B, num_nodes);
}

// round 14
// speedup vs baseline: 2.0637x; 1.1053x over previous
#include <cuda_runtime.h>
#include <math.h>

#define FEAT   512
#define HID    512
#define KNB    25
#define ALPHA  0.2f
#define GPC    32      // central nodes (agg rows) per CTA, one per warp
#define NTHR   1024    // 32 warps
#define ASTRIDE 516    // s_agg row stride in words (bank-conflict-free A frags)
#define MAXN   100352  // capacity for per-node score tables

// small scratch globals (4 KB ok — proven; 800 KB total here)
__device__ __align__(16) float g_w1[FEAT];
__device__ __align__(16) float g_w2[FEAT];
__device__ __align__(16) float g_s1[MAXN];   // feat[n] . w1
__device__ __align__(16) float g_s2[MAXN];   // feat[n] . w2

// ---------------- kernel 1: w1 = W @ a[:H], w2 = W @ a[H:] -------------------
__global__ void wvec_kernel(const float* __restrict__ W,
                            const float* __restrict__ a_vec) {
    const int wid  = threadIdx.x >> 5;
    const int lane = threadIdx.x & 31;
    const int f    = blockIdx.x * 8 + wid;
    if (f >= FEAT) return;
    const float* row = W + (size_t)f * HID;
    float a1 = 0.f, a2 = 0.f;
    #pragma unroll
    for (int j = 0; j < 4; j++) {
        int i = lane * 4 + 128 * j;
        float4 w  = *(const float4*)(row + i);
        float4 v1 = *(const float4*)(a_vec + i);
        float4 v2 = *(const float4*)(a_vec + HID + i);
        a1 += w.x * v1.x + w.y * v1.y + w.z * v1.z + w.w * v1.w;
        a2 += w.x * v2.x + w.y * v2.y + w.z * v2.z + w.w * v2.w;
    }
    #pragma unroll
    for (int o = 16; o; o >>= 1) {
        a1 += __shfl_xor_sync(0xffffffffu, a1, o);
        a2 += __shfl_xor_sync(0xffffffffu, a2, o);
    }
    if (lane == 0) { g_w1[f] = a1; g_w2[f] = a2; }
}

// ---------------- kernel 2: per-node scores s1[n], s2[n] ---------------------
// One warp per node row; streams the whole feature table once (~200 MB).
__global__ __launch_bounds__(256)
void sdot_kernel(const float* __restrict__ feat, int num_nodes) {
    __shared__ __align__(16) float s_w1[FEAT];
    __shared__ __align__(16) float s_w2[FEAT];
    if (threadIdx.x < 128) {
        int i = threadIdx.x * 4;
        *(float4*)(s_w1 + i) = *(const float4*)(g_w1 + i);
    } else {
        int i = (threadIdx.x - 128) * 4;
        *(float4*)(s_w2 + i) = *(const float4*)(g_w2 + i);
    }
    __syncthreads();

    const int wid  = threadIdx.x >> 5;
    const int lane = threadIdx.x & 31;
    const int n    = blockIdx.x * 8 + wid;
    if (n >= num_nodes) return;

    const float* src = feat + (size_t)n * FEAT;
    float p1 = 0.f, p2 = 0.f;
    #pragma unroll
    for (int j = 0; j < 4; j++) {
        int i = lane * 4 + 128 * j;
        float4 v  = *(const float4*)(src + i);
        float4 w1 = *(const float4*)(s_w1 + i);
        float4 w2 = *(const float4*)(s_w2 + i);
        p1 += v.x * w1.x + v.y * w1.y + v.z * w1.z + v.w * w1.w;
        p2 += v.x * w2.x + v.y * w2.y + v.z * w2.z + v.w * w2.w;
    }
    #pragma unroll
    for (int o = 16; o; o >>= 1) {
        p1 += __shfl_xor_sync(0xffffffffu, p1, o);
        p2 += __shfl_xor_sync(0xffffffffu, p2, o);
    }
    if (lane == 0) { g_s1[n] = p1; g_s2[n] = p2; }
}

__device__ __forceinline__ unsigned f2tf32(float f) {
    unsigned u;
    asm("cvt.rna.tf32.f32 %0, %1;" : "=r"(u) : "f"(f));
    return u;
}

__device__ __forceinline__ void mma_tf32(float& d0, float& d1, float& d2, float& d3,
                                         unsigned a0, unsigned a1, unsigned a2, unsigned a3,
                                         unsigned b0, unsigned b1) {
    asm volatile(
        "mma.sync.aligned.m16n8k8.row.col.f32.tf32.tf32.f32 "
        "{%0,%1,%2,%3},{%4,%5,%6,%7},{%8,%9},{%0,%1,%2,%3};"
        : "+f"(d0), "+f"(d1), "+f"(d2), "+f"(d3)
        : "r"(a0), "r"(a1), "r"(a2), "r"(a3), "r"(b0), "r"(b1));
}

// ---------------- kernel 3: fused gather-agg + tf32 GEMM + relu --------------
// Edge weights from precomputed s1/s2 (no per-row dot/reduce). Main loop is
// pure streaming: load 2 rows -> acc += e*v. 32 warps, warp w owns agg row w.
__global__ __launch_bounds__(NTHR, 1)
void fused_kernel(const int*   __restrict__ nodes,
                  const int*   __restrict__ neigh,
                  const float* __restrict__ feat,
                  const float* __restrict__ W,
                  float*       __restrict__ out,
                  int B, int num_nodes) {
    __shared__ unsigned s_agg[GPC * ASTRIDE];   // tf32 bits, 66 KB
    __shared__ int   s_idx[GPC][26];
    __shared__ float s_e[GPC][KNB];

    const int wid  = threadIdx.x >> 5;          // 0..31 == agg row
    const int lane = threadIdx.x & 31;
    const int base = blockIdx.x * GPC;
    const int b    = base + wid;

    if (b < B) {
        // ---- indices + edge weights, all before any feature-row load ----
        int myidx = 0;
        if (lane < 26) {
            int idx = (lane == 0) ? nodes[b] : neigh[b * KNB + (lane - 1)];
            myidx = min(max(idx, 0), num_nodes - 1);
            s_idx[wid][lane] = myidx;
        }
        __syncwarp();

        float sct = g_s1[s_idx[wid][0]];        // uniform load, L1-broadcast
        float e = 0.f;
        if (lane >= 1 && lane < 26) {
            float lg = sct + g_s2[myidx];
            float lr = (lg > 0.f) ? lg : ALPHA * lg;
            e = __expf(-lr);
        }
        float tot = e;
        #pragma unroll
        for (int o = 16; o; o >>= 1)
            tot += __shfl_xor_sync(0xffffffffu, tot, o);
        if (lane >= 1 && lane < 26)
            s_e[wid][lane - 1] = e / tot;       // normalized attn weight
        __syncwarp();

        // ---- streaming aggregation: 2 rows per iteration, no reductions ----
        float4 acc[4];
        #pragma unroll
        for (int j = 0; j < 4; j++) acc[j] = make_float4(0.f, 0.f, 0.f, 0.f);

        for (int k = 0; k < KNB - 1; k += 2) {
            float e0 = s_e[wid][k];
            float e1 = s_e[wid][k + 1];
            const float* s0 = feat + (size_t)s_idx[wid][1 + k] * FEAT;
            const float* s1 = feat + (size_t)s_idx[wid][2 + k] * FEAT;
            float4 v0[4], v1[4];
            #pragma unroll
            for (int j = 0; j < 4; j++) {
                int i = lane * 4 + 128 * j;
                v0[j] = *(const float4*)(s0 + i);
                v1[j] = *(const float4*)(s1 + i);
            }
            #pragma unroll
            for (int j = 0; j < 4; j++) {
                acc[j].x += e0 * v0[j].x + e1 * v1[j].x;
                acc[j].y += e0 * v0[j].y + e1 * v1[j].y;
                acc[j].z += e0 * v0[j].z + e1 * v1[j].z;
                acc[j].w += e0 * v0[j].w + e1 * v1[j].w;
            }
        }
        {   // tail neighbor (k = 24)
            float e0 = s_e[wid][KNB - 1];
            const float* s0 = feat + (size_t)s_idx[wid][KNB] * FEAT;
            #pragma unroll
            for (int j = 0; j < 4; j++) {
                float4 v = *(const float4*)(s0 + lane * 4 + 128 * j);
                acc[j].x += e0 * v.x;  acc[j].y += e0 * v.y;
                acc[j].z += e0 * v.z;  acc[j].w += e0 * v.w;
            }
        }

        #pragma unroll
        for (int j = 0; j < 4; j++) {
            int c = lane * 4 + 128 * j;
            unsigned* dst = &s_agg[wid * ASTRIDE + c];
            dst[0] = f2tf32(acc[j].x);
            dst[1] = f2tf32(acc[j].y);
            dst[2] = f2tf32(acc[j].z);
            dst[3] = f2tf32(acc[j].w);
        }
    } else {
        #pragma unroll
        for (int j = 0; j < 16; j++)
            s_agg[wid * ASTRIDE + lane + 32 * j] = 0u;
    }
    __syncthreads();

    // ============ epilogue: relu(s_agg[32x512] @ W) via tf32 mma ============
    const int gid = lane >> 2;          // 0..7
    const int tig = lane & 3;           // 0..3
    const int n0  = wid * 16;

    float cacc[2][2][4];
    #pragma unroll
    for (int r = 0; r < 2; r++)
        #pragma unroll
        for (int t = 0; t < 2; t++)
            #pragma unroll
            for (int q = 0; q < 4; q++) cacc[r][t][q] = 0.f;

    for (int k0 = 0; k0 < FEAT; k0 += 8) {
        const int ka = k0 + tig;
        const float* wr0 = W + (size_t)ka * HID;
        const float* wr1 = wr0 + (size_t)4 * HID;
        unsigned bf[2][2];
        #pragma unroll
        for (int t = 0; t < 2; t++) {
            int n = n0 + t * 8 + gid;
            bf[t][0] = f2tf32(wr0[n]);
            bf[t][1] = f2tf32(wr1[n]);
        }
        #pragma unroll
        for (int r = 0; r < 2; r++) {
            int row0 = gid + 16 * r;
            unsigned a0 = s_agg[row0 * ASTRIDE + ka];
            unsigned a1 = s_agg[(row0 + 8) * ASTRIDE + ka];
            unsigned a2 = s_agg[row0 * ASTRIDE + ka + 4];
            unsigned a3 = s_agg[(row0 + 8) * ASTRIDE + ka + 4];
            #pragma unroll
            for (int t = 0; t < 2; t++)
                mma_tf32(cacc[r][t][0], cacc[r][t][1], cacc[r][t][2], cacc[r][t][3],
                         a0, a1, a2, a3, bf[t][0], bf[t][1]);
        }
    }

    #pragma unroll
    for (int r = 0; r < 2; r++) {
        const int bb0 = base + gid + 16 * r;
        const int bb1 = bb0 + 8;
        #pragma unroll
        for (int t = 0; t < 2; t++) {
            int col = n0 + t * 8 + 2 * tig;
            if (bb0 < B) {
                float2 o;
                o.x = fmaxf(cacc[r][t][0], 0.f);
                o.y = fmaxf(cacc[r][t][1], 0.f);
                *(float2*)(out + (size_t)bb0 * HID + col) = o;
            }
            if (bb1 < B) {
                float2 o;
                o.x = fmaxf(cacc[r][t][2], 0.f);
                o.y = fmaxf(cacc[r][t][3], 0.f);
                *(float2*)(out + (size_t)bb1 * HID + col) = o;
            }
        }
    }
}

// ---------------- launch -----------------------------------------------------
// Inputs identified by element count (all six distinct):
//   nodes: 20000   neigh: 500000   feat: 51,200,000   W: 262144
//   a_vec: 1024    U: 729 (unused; eigh eigenvectors orthonormal => U@U^T = I)
extern "C" void kernel_launch(void* const* d_in, const int* in_sizes, int n_in,
                              void* d_out, int out_size) {
    const int*   nodes = nullptr;
    const int*   neigh = nullptr;
    const float* feat  = nullptr;
    const float* W     = nullptr;
    const float* a_vec = nullptr;
    long feat_elems = 0;

    long idx_sz[2] = {0, 0};
    const void* idx_ptr[2] = {nullptr, nullptr};
    int n_idx = 0;
    for (int i = 0; i < n_in; i++) {
        long n = in_sizes[i];
        if (n == 729) {
            // U — unused
        } else if (n == 1024) {
            a_vec = (const float*)d_in[i];
        } else if (n == 262144) {
            W = (const float*)d_in[i];
        } else if (n >= 1000000 && (n % FEAT) == 0) {
            feat = (const float*)d_in[i];
            feat_elems = n;
        } else if (n_idx < 2) {
            idx_sz[n_idx] = n; idx_ptr[n_idx] = d_in[i]; n_idx++;
        }
    }
    long nodes_n;
    if (idx_sz[0] <= idx_sz[1]) {
        nodes = (const int*)idx_ptr[0]; nodes_n = idx_sz[0];
        neigh = (const int*)idx_ptr[1];
    } else {
        nodes = (const int*)idx_ptr[1]; nodes_n = idx_sz[1];
        neigh = (const int*)idx_ptr[0];
    }

    float* out = (float*)d_out;
    int B = (int)nodes_n;
    int num_nodes = (int)(feat_elems / FEAT);
    if (num_nodes > MAXN) num_nodes = MAXN;

    wvec_kernel<<<64, 256>>>(W, a_vec);
    sdot_kernel<<<(num_nodes + 7) / 8, 256>>>(feat, num_nodes);
    fused_kernel<<<(B + GPC - 1) / GPC, NTHR>>>(nodes, neigh, feat, W, out,
                                                B, num_nodes);
}